// round 12
// baseline (speedup 1.0000x reference)
#include <cuda_runtime.h>

#define B_   4
#define N_   256
#define DM_  128
#define DE_  8
#define H_   8
#define D_   16
#define L_   2
#define BN_  (B_ * N_)
#define SCALE 0.25f   // 1/sqrt(16)
#define GRID 128      // < 148 SMs -> all CTAs resident even at 1 CTA/SM
#define NT   512

typedef unsigned long long ull;

// -------------------- scratch (no allocation allowed) --------------------
__device__ float g_Q[BN_ * DM_];
__device__ float g_K[BN_ * DM_];
__device__ float g_V[BN_ * DM_];
__device__ float g_RES[BN_ * DM_];
__device__ float g_OUT[BN_ * DM_];
__device__ float g_X[BN_ * DM_];
__device__ float g_means[N_];
__device__ unsigned g_bar;

// -------------------- f32x2 packed helpers --------------------
__device__ __forceinline__ ull pack2(float lo, float hi) {
    ull r;
    asm("mov.b64 %0, {%1, %2};" : "=l"(r) : "f"(lo), "f"(hi));
    return r;
}
__device__ __forceinline__ void fma2(ull& d, ull a, ull b) {
    asm("fma.rn.f32x2 %0, %1, %2, %0;" : "+l"(d) : "l"(a), "l"(b));
}
__device__ __forceinline__ void unpack2(ull v, float& lo, float& hi) {
    asm("mov.b64 {%0, %1}, %2;" : "=f"(lo), "=f"(hi) : "l"(v));
}

__device__ __forceinline__ float warp_allreduce(float v) {
    #pragma unroll
    for (int o = 16; o > 0; o >>= 1) v += __shfl_xor_sync(0xffffffffu, v, o);
    return v;
}

// -------------------- smem union across phases --------------------
struct AttnS {
    float4 ks4[D_ / 4][N_];     // 16 KB  [d-quad][j]
    float4 vs4[D_ / 4][N_];     // 16 KB
    float  qs[64][D_];          // 4 KB
    float  qwe[64][DE_];        // 2 KB
    float  qbe[64];
    float  mloc[64];
    float  tot[16][2][25];      // [warp][half][q]
};
struct ProjS  { float2 xs[DM_][4]; };                 // [col][row-pair]
struct MeansS { float qs[2][D_]; float qwe[2][DE_]; float qbe[2]; float wsum[2][8]; };
union SmemU { AttnS a; ProjS p; MeansS m; };

// ---- grid barrier: RED arrive (unused atomic result) + volatile LDG poll ----
__device__ __forceinline__ void grid_barrier(unsigned target) {
    __syncthreads();
    if (threadIdx.x == 0) {
        __threadfence();
        atomicAdd(&g_bar, 1u);                     // result unused -> RED
        const volatile unsigned* p = &g_bar;       // plain L2 load poll
        while (*p < target) __nanosleep(32);
        __threadfence();
    }
    __syncthreads();
}

__global__ void reset_bar_kernel() { g_bar = 0u; }

// ============================================================================
__global__ void __launch_bounds__(NT)
mega_kernel(const float* __restrict__ nodes,
            const float* __restrict__ edges,
            const float* __restrict__ adjacency,
            const float* __restrict__ Wq, const float* __restrict__ bq,
            const float* __restrict__ Wk, const float* __restrict__ bk,
            const float* __restrict__ Wv, const float* __restrict__ bv,
            const float* __restrict__ We, const float* __restrict__ be,
            const float* __restrict__ Wr, const float* __restrict__ br,
            const float* __restrict__ Wg,
            const float* __restrict__ lng, const float* __restrict__ lnb,
            float* __restrict__ out)
{
    __shared__ SmemU sm;
    const int t = threadIdx.x;
    const int lane = t & 31, warp = t >> 5;
    unsigned tgt = 0;

    for (int l = 0; l < L_; l++) {
        const float* lWq = Wq + l * DM_ * DM_;  const float* lbq = bq + l * DM_;
        const float* lWk = Wk + l * DM_ * DM_;  const float* lbk = bk + l * DM_;
        const float* lWv = Wv + l * DM_ * DM_;  const float* lbv = bv + l * DM_;
        const float* lWe = We + l * DE_ * DM_;  const float* lbe = be + l * DM_;
        const float* lWr = Wr + l * DM_ * DM_;  const float* lbr = br + l * DM_;
        const float* lWg = Wg + l * 3 * DM_;
        const float* llng = lng + l * DM_;      const float* llnb = lnb + l * DM_;

        // ============ phase 1: fused Q/K/V/RES projection (8 rows/block) ======
        {
            const int col = t & 127, pr = t >> 7;       // pr -> rows {2pr, 2pr+1}
            const int row0 = blockIdx.x * 8;
            const int r = row0 + 2 * pr;
            const float* x = l ? g_X : nodes;
            sm.p.xs[col][pr] = make_float2(__ldcg(x + r * DM_ + col),
                                           __ldcg(x + (r + 1) * DM_ + col));
            __syncthreads();

            ull aq = pack2(lbq[col], lbq[col]);
            ull ak = pack2(lbk[col], lbk[col]);
            ull av = pack2(lbv[col], lbv[col]);
            ull ar = pack2(lbr[col], lbr[col]);

            #pragma unroll 4
            for (int c = 0; c < DM_; c++) {
                const float wq = lWq[c * DM_ + col];
                const float wk = lWk[c * DM_ + col];
                const float wv = lWv[c * DM_ + col];
                const float wr = lWr[c * DM_ + col];
                const float2 xp = sm.p.xs[c][pr];
                const ull x2 = pack2(xp.x, xp.y);
                fma2(aq, x2, pack2(wq, wq));
                fma2(ak, x2, pack2(wk, wk));
                fma2(av, x2, pack2(wv, wv));
                fma2(ar, x2, pack2(wr, wr));
            }
            float lo, hi;
            const int r0 = r * DM_ + col;
            unpack2(aq, lo, hi); g_Q[r0] = lo;   g_Q[r0 + DM_] = hi;
            unpack2(ak, lo, hi); g_K[r0] = lo;   g_K[r0 + DM_] = hi;
            unpack2(av, lo, hi); g_V[r0] = lo;   g_V[r0 + DM_] = hi;
            unpack2(ar, lo, hi); g_RES[r0] = lo; g_RES[r0 + DM_] = hi;
        }
        tgt += GRID; grid_barrier(tgt);

        // ============ phase 2: sim row means for bh==0 (2 i's/block) ==========
        {
            const int grp = t >> 8, j = t & 255;
            const int i = blockIdx.x * 2 + grp;
            const int gw = warp & 7;
            if (j < D_) sm.m.qs[grp][j] = __ldcg(&g_Q[i * DM_ + j]);   // b=0,h=0
            __syncthreads();
            if (j < DE_) {
                float s = 0.f;
                #pragma unroll
                for (int d = 0; d < D_; d++) s = fmaf(sm.m.qs[grp][d], lWe[j * DM_ + d], s);
                sm.m.qwe[grp][j] = s;
            } else if (j == DE_) {
                float s = 0.f;
                #pragma unroll
                for (int d = 0; d < D_; d++) s = fmaf(sm.m.qs[grp][d], lbe[d], s);
                sm.m.qbe[grp] = s;
            }
            __syncthreads();

            float sim = sm.m.qbe[grp];
            const float4* kp = (const float4*)&g_K[j * DM_];          // b=0,h=0
            #pragma unroll
            for (int q4 = 0; q4 < 4; q4++) {
                const float4 kk = __ldcg(kp + q4);
                sim = fmaf(sm.m.qs[grp][4*q4+0], kk.x, sim);
                sim = fmaf(sm.m.qs[grp][4*q4+1], kk.y, sim);
                sim = fmaf(sm.m.qs[grp][4*q4+2], kk.z, sim);
                sim = fmaf(sm.m.qs[grp][4*q4+3], kk.w, sim);
            }
            const float4* epp = (const float4*)(edges + ((size_t)i * N_ + j) * DE_);
            const float4 e0 = __ldcg(epp), e1 = __ldcg(epp + 1);
            sim = fmaf(e0.x, sm.m.qwe[grp][0], sim);
            sim = fmaf(e0.y, sm.m.qwe[grp][1], sim);
            sim = fmaf(e0.z, sm.m.qwe[grp][2], sim);
            sim = fmaf(e0.w, sm.m.qwe[grp][3], sim);
            sim = fmaf(e1.x, sm.m.qwe[grp][4], sim);
            sim = fmaf(e1.y, sm.m.qwe[grp][5], sim);
            sim = fmaf(e1.z, sm.m.qwe[grp][6], sim);
            sim = fmaf(e1.w, sm.m.qwe[grp][7], sim);
            sim *= SCALE;

            #pragma unroll
            for (int o = 16; o > 0; o >>= 1) sim += __shfl_down_sync(0xffffffffu, sim, o);
            if (lane == 0) sm.m.wsum[grp][gw] = sim;
            __syncthreads();
            if (j == 0) {
                float s = 0.f;
                #pragma unroll
                for (int w = 0; w < 8; w++) s += sm.m.wsum[grp][w];
                g_means[i] = s * (1.0f / N_);
            }
        }
        tgt += GRID; grid_barrier(tgt);

        // ============ phase 3: attention — (b,h) per block, half-warp pairs ====
        {
            const int pairIdx = blockIdx.x >> 2;        // 0..31
            const int b = pairIdx >> 3, h = pairIdx & 7;
            const int i_base = (blockIdx.x & 3) * 64;
            const int hf = lane >> 4;                   // half-warp id
            const int sl = lane & 15;                   // sub-lane

            // K/V tile + q tile loads
            {
                const int j = t & 255;
                if (t < 256) {
                    const float4* kp = (const float4*)(g_K + (b * N_ + j) * DM_ + h * D_);
                    #pragma unroll
                    for (int q4 = 0; q4 < 4; q4++) sm.a.ks4[q4][j] = __ldcg(kp + q4);
                } else {
                    const float4* vp = (const float4*)(g_V + (b * N_ + j) * DM_ + h * D_);
                    #pragma unroll
                    for (int q4 = 0; q4 < 4; q4++) sm.a.vs4[q4][j] = __ldcg(vp + q4);
                }
                #pragma unroll
                for (int rep = 0; rep < 2; rep++) {
                    const int idx = t + rep * NT;
                    const int ii = idx >> 4, dd = idx & 15;
                    sm.a.qs[ii][dd] =
                        __ldcg(&g_Q[(b * N_ + i_base + ii) * DM_ + h * D_ + dd]);
                }
                if (t < 64) sm.a.mloc[t] = __ldcg(&g_means[i_base + t]);
            }
            __syncthreads();
            {
                const int ii = t >> 3, c = t & 7;       // 512 = 64 x 8
                float s = 0.f;
                #pragma unroll
                for (int d = 0; d < D_; d++)
                    s = fmaf(sm.a.qs[ii][d], lWe[c * DM_ + h * D_ + d], s);
                sm.a.qwe[ii][c] = s;
                if (t < 64) {
                    float sb = 0.f;
                    #pragma unroll
                    for (int d = 0; d < D_; d++)
                        sb = fmaf(sm.a.qs[t][d], lbe[h * D_ + d], sb);
                    sm.a.qbe[t] = sb;
                }
            }
            __syncthreads();

            // each warp: 4 rows as 2 half-warp pairs
            for (int pr = 0; pr < 2; pr++) {
                const int ii = warp * 4 + pr * 2 + hf;  // this half-warp's row
                const int i  = i_base + ii;

                ull q2[8], qw2[4], av2[8], ae2[4];
                #pragma unroll
                for (int d2 = 0; d2 < 8; d2++) {
                    q2[d2]  = pack2(sm.a.qs[ii][2*d2], sm.a.qs[ii][2*d2+1]);
                    av2[d2] = pack2(0.f, 0.f);
                }
                #pragma unroll
                for (int c2 = 0; c2 < 4; c2++) {
                    qw2[c2] = pack2(sm.a.qwe[ii][2*c2], sm.a.qwe[ii][2*c2+1]);
                    ae2[c2] = pack2(0.f, 0.f);
                }
                const float qb   = sm.a.qbe[ii];
                const float mval = sm.a.mloc[ii];
                float ap = 0.f;
                const float4* ep  = (const float4*)(edges + (size_t)(b * N_ + i) * N_ * DE_);
                const float*  adp = adjacency + ((size_t)b * N_ + i) * N_;

                // 2-deep software pipeline: buffers A (chunk ch) and B (chunk ch+1)
                float4 A0 = __ldcg(ep + 2 * sl),  A1 = __ldcg(ep + 2 * sl + 1);
                float  Aa = __ldcg(adp + sl);
                float4 B0 = __ldcg(ep + 2 * (sl + 16)), B1 = __ldcg(ep + 2 * (sl + 16) + 1);
                float  Ba = __ldcg(adp + sl + 16);

                #pragma unroll
                for (int ch = 0; ch < 16; ch += 2) {
                    // ---- even chunk: process A, prefetch ch+2 into A ----
                    {
                        const int j = ch * 16 + sl;
                        float4 nA0, nA1; float nAa = 0.f;
                        if (ch + 2 < 16) {
                            nA0 = __ldcg(ep + 2 * (j + 32));
                            nA1 = __ldcg(ep + 2 * (j + 32) + 1);
                            nAa = __ldcg(adp + j + 32);
                        }
                        ull e2[4];
                        e2[0] = pack2(A0.x, A0.y); e2[1] = pack2(A0.z, A0.w);
                        e2[2] = pack2(A1.x, A1.y); e2[3] = pack2(A1.z, A1.w);

                        ull s2a = pack2(qb, 0.f);
                        ull s2b = pack2(0.f, 0.f);
                        #pragma unroll
                        for (int d4 = 0; d4 < 4; d4++) {
                            const float4 kk = sm.a.ks4[d4][j];
                            fma2(s2a, q2[2*d4],     pack2(kk.x, kk.y));
                            fma2(s2b, q2[2*d4 + 1], pack2(kk.z, kk.w));
                        }
                        fma2(s2a, qw2[0], e2[0]); fma2(s2b, qw2[1], e2[1]);
                        fma2(s2a, qw2[2], e2[2]); fma2(s2b, qw2[3], e2[3]);
                        float alo, ahi, blo, bhi;
                        unpack2(s2a, alo, ahi); unpack2(s2b, blo, bhi);
                        const float p = __expf((alo + ahi + blo + bhi) * SCALE - mval) * Aa;
                        const ull pp = pack2(p, p);
                        ap += p;
                        #pragma unroll
                        for (int d4 = 0; d4 < 4; d4++) {
                            const float4 vv = sm.a.vs4[d4][j];
                            fma2(av2[2*d4],     pp, pack2(vv.x, vv.y));
                            fma2(av2[2*d4 + 1], pp, pack2(vv.z, vv.w));
                        }
                        #pragma unroll
                        for (int c2 = 0; c2 < 4; c2++) fma2(ae2[c2], pp, e2[c2]);
                        A0 = nA0; A1 = nA1; Aa = nAa;
                    }
                    // ---- odd chunk: process B, prefetch ch+3 into B ----
                    {
                        const int j = (ch + 1) * 16 + sl;
                        float4 nB0, nB1; float nBa = 0.f;
                        if (ch + 3 < 16) {
                            nB0 = __ldcg(ep + 2 * (j + 32));
                            nB1 = __ldcg(ep + 2 * (j + 32) + 1);
                            nBa = __ldcg(adp + j + 32);
                        }
                        ull e2[4];
                        e2[0] = pack2(B0.x, B0.y); e2[1] = pack2(B0.z, B0.w);
                        e2[2] = pack2(B1.x, B1.y); e2[3] = pack2(B1.z, B1.w);

                        ull s2a = pack2(qb, 0.f);
                        ull s2b = pack2(0.f, 0.f);
                        #pragma unroll
                        for (int d4 = 0; d4 < 4; d4++) {
                            const float4 kk = sm.a.ks4[d4][j];
                            fma2(s2a, q2[2*d4],     pack2(kk.x, kk.y));
                            fma2(s2b, q2[2*d4 + 1], pack2(kk.z, kk.w));
                        }
                        fma2(s2a, qw2[0], e2[0]); fma2(s2b, qw2[1], e2[1]);
                        fma2(s2a, qw2[2], e2[2]); fma2(s2b, qw2[3], e2[3]);
                        float alo, ahi, blo, bhi;
                        unpack2(s2a, alo, ahi); unpack2(s2b, blo, bhi);
                        const float p = __expf((alo + ahi + blo + bhi) * SCALE - mval) * Ba;
                        const ull pp = pack2(p, p);
                        ap += p;
                        #pragma unroll
                        for (int d4 = 0; d4 < 4; d4++) {
                            const float4 vv = sm.a.vs4[d4][j];
                            fma2(av2[2*d4],     pp, pack2(vv.x, vv.y));
                            fma2(av2[2*d4 + 1], pp, pack2(vv.z, vv.w));
                        }
                        #pragma unroll
                        for (int c2 = 0; c2 < 4; c2++) fma2(ae2[c2], pp, e2[c2]);
                        B0 = nB0; B1 = nB1; Ba = nBa;
                    }
                }

                float red[25];
                #pragma unroll
                for (int d2 = 0; d2 < 8; d2++) unpack2(av2[d2], red[2*d2], red[2*d2+1]);
                #pragma unroll
                for (int c2 = 0; c2 < 4; c2++) unpack2(ae2[c2], red[16+2*c2], red[17+2*c2]);
                red[24] = ap;
                // half-warp tree: offsets 8,4,2,1; results valid at lanes 0 and 16
                #pragma unroll
                for (int q = 0; q < 25; q++) {
                    float v = red[q];
                    #pragma unroll
                    for (int o = 8; o > 0; o >>= 1) v += __shfl_down_sync(0xffffffffu, v, o);
                    red[q] = v;
                }
                if (sl == 0) {
                    #pragma unroll
                    for (int q = 0; q < 25; q++) sm.a.tot[warp][hf][q] = red[q];
                }
                __syncwarp();
                {
                    // all 32 lanes: half hf outputs its row, dims sl (0..15)
                    const float sv  = sm.a.tot[warp][hf][24];
                    const float inv = (sv == 0.f) ? 1.f : (1.f / sv);
                    float o = sm.a.tot[warp][hf][sl] + sv * lbe[h * D_ + sl];
                    #pragma unroll
                    for (int c = 0; c < DE_; c++)
                        o = fmaf(sm.a.tot[warp][hf][16 + c], lWe[c * DM_ + h * D_ + sl], o);
                    g_OUT[(b * N_ + i) * DM_ + h * D_ + sl] = o * inv;
                }
                __syncwarp();
            }
        }
        tgt += GRID; grid_barrier(tgt);

        // ============ phase 4: gate + gated residual + LN + ReLU ==============
        if (warp < 8) {
            const int row = blockIdx.x * 8 + warp;
            const int c0 = lane * 4;

            const float4 o4 = __ldcg((const float4*)(g_OUT + row * DM_ + c0));
            const float4 r4 = __ldcg((const float4*)(g_RES + row * DM_ + c0));
            const float o[4] = {o4.x, o4.y, o4.z, o4.w};
            const float r[4] = {r4.x, r4.y, r4.z, r4.w};

            const float4 w0 = *(const float4*)(lWg + c0);
            const float4 w1 = *(const float4*)(lWg + DM_ + c0);
            const float4 w2 = *(const float4*)(lWg + 2 * DM_ + c0);

            float gpart = o[0]*w0.x + r[0]*w1.x + (o[0]-r[0])*w2.x
                        + o[1]*w0.y + r[1]*w1.y + (o[1]-r[1])*w2.y
                        + o[2]*w0.z + r[2]*w1.z + (o[2]-r[2])*w2.z
                        + o[3]*w0.w + r[3]*w1.w + (o[3]-r[3])*w2.w;
            const float gdot = warp_allreduce(gpart);
            const float g = 1.0f / (1.0f + __expf(-gdot));

            float y[4], ysum = 0.f;
            #pragma unroll
            for (int k = 0; k < 4; k++) { y[k] = o[k] * g + r[k] * (1.0f - g); ysum += y[k]; }
            const float mu = warp_allreduce(ysum) * (1.0f / DM_);

            float vsum = 0.f;
            #pragma unroll
            for (int k = 0; k < 4; k++) { const float d = y[k] - mu; vsum += d * d; }
            const float rstd = rsqrtf(warp_allreduce(vsum) * (1.0f / DM_) + 1e-5f);

            const float4 g4 = *(const float4*)(llng + c0);
            const float4 b4 = *(const float4*)(llnb + c0);
            float4 res;
            res.x = fmaxf((y[0] - mu) * rstd * g4.x + b4.x, 0.f);
            res.y = fmaxf((y[1] - mu) * rstd * g4.y + b4.y, 0.f);
            res.z = fmaxf((y[2] - mu) * rstd * g4.z + b4.z, 0.f);
            res.w = fmaxf((y[3] - mu) * rstd * g4.w + b4.w, 0.f);

            float* dst = (l < L_ - 1) ? g_X : out;
            *(float4*)(dst + row * DM_ + c0) = res;
        }
        if (l == 0) { tgt += GRID; grid_barrier(tgt); }
    }
}

// -------------------- launch --------------------
extern "C" void kernel_launch(void* const* d_in, const int* in_sizes, int n_in,
                              void* d_out, int out_size)
{
    const float* nodes = (const float*)d_in[0];
    const float* edges = (const float*)d_in[1];
    const float* adj   = (const float*)d_in[2];
    const float* Wq = (const float*)d_in[3];
    const float* bq = (const float*)d_in[4];
    const float* Wk = (const float*)d_in[5];
    const float* bk = (const float*)d_in[6];
    const float* Wv = (const float*)d_in[7];
    const float* bv = (const float*)d_in[8];
    const float* We = (const float*)d_in[9];
    const float* be = (const float*)d_in[10];
    const float* Wr = (const float*)d_in[11];
    const float* br = (const float*)d_in[12];
    const float* Wg = (const float*)d_in[13];
    const float* lng = (const float*)d_in[14];
    const float* lnb = (const float*)d_in[15];
    float* out = (float*)d_out;

    reset_bar_kernel<<<1, 1>>>();
    mega_kernel<<<GRID, NT>>>(nodes, edges, adj, Wq, bq, Wk, bk, Wv, bv,
                              We, be, Wr, br, Wg, lng, lnb, out);
}